// round 1
// baseline (speedup 1.0000x reference)
#include <cuda_runtime.h>
#include <cuda_bf16.h>
#include <math.h>

// ---------------- problem constants ----------------
#define BATCH      16
#define SEQ        2048
#define NTOK       (BATCH*SEQ)          // 32768
#define INPUT_DIM  1024
#define HIDDEN     256
#define D_STATE    32
#define D_INNER    512
#define NHEADS     16
#define HEADDIM    32
#define CONV_DIM   576                  // D_INNER + 2*D_STATE
#define D_IN_PROJ  1104                 // 2*D_INNER + 2*D_STATE + NHEADS
#define KCONV      4
#define EPS        1e-5f

// ---------------- scratch (device globals; no allocation allowed) ----------
__device__ __align__(128) float g_act [NTOK*HIDDEN];      // current activations (256)
__device__ __align__(128) float g_z   [NTOK*D_IN_PROJ];   // in-proj output (1104)
__device__ __align__(128) float g_xbc [NTOK*CONV_DIM];    // conv+silu output (576)
__device__ __align__(128) float g_dt  [NTOK*NHEADS];      // softplus(dt)
__device__ __align__(128) float g_dA  [NTOK*NHEADS];      // exp(dt*A)
__device__ __align__(128) float g_y   [NTOK*D_INNER];     // scan output / mlp hidden (512)
__device__ __align__(128) float g_o   [NTOK*HIDDEN];      // out-proj result / ln buffers (256)

// ---------------- helpers ----------------
__device__ __forceinline__ float blockSum(float v) {
    __shared__ float sh[8];
    __shared__ float total;
    int lane = threadIdx.x & 31, wid = threadIdx.x >> 5;
    #pragma unroll
    for (int o = 16; o > 0; o >>= 1) v += __shfl_xor_sync(0xffffffffu, v, o);
    if (lane == 0) sh[wid] = v;
    __syncthreads();
    if (threadIdx.x == 0) {
        float t = 0.f;
        int nw = (int)(blockDim.x >> 5);
        for (int i = 0; i < nw; i++) t += sh[i];
        total = t;
    }
    __syncthreads();
    return total;
}

__device__ __forceinline__ float siluf(float x) { return x / (1.f + expf(-x)); }

// ---------------- generic SGEMM: C = A[MxK] @ W[KxN] + bias, optional GELU ---
// BM=128 BN=64 BK=16, 256 threads, 8x4 per-thread tile.
template<int EPI>
__global__ void __launch_bounds__(256)
sgemm_kernel(const float* __restrict__ A, const float* __restrict__ W,
             const float* __restrict__ bias, float* __restrict__ C,
             int M, int N, int K)
{
    const int BM = 128, BN = 64, BK = 16;
    __shared__ float As[BK][BM];
    __shared__ float Ws[BK][BN];
    int tid = threadIdx.x;
    int tx = tid & 15;          // column group 0..15
    int ty = tid >> 4;          // row group 0..15
    int row0 = blockIdx.y * BM;
    int col0 = blockIdx.x * BN;

    float acc[8][4];
    #pragma unroll
    for (int i = 0; i < 8; i++)
        #pragma unroll
        for (int j = 0; j < 4; j++) acc[i][j] = 0.f;

    int ar0 = tid >> 2;         // 0..63
    int akq = tid & 3;          // which float4 along K
    int wrow = tid >> 4;        // 0..15
    int wc4  = tid & 15;        // which float4 along N

    for (int kt = 0; kt < K; kt += BK) {
        // A tile (coalesced float4 loads, transposed store)
        #pragma unroll
        for (int h = 0; h < 2; h++) {
            int r = ar0 + h * 64;
            const float4 av = *reinterpret_cast<const float4*>(
                &A[(size_t)(row0 + r) * K + kt + akq * 4]);
            As[akq*4+0][r] = av.x;
            As[akq*4+1][r] = av.y;
            As[akq*4+2][r] = av.z;
            As[akq*4+3][r] = av.w;
        }
        // W tile
        {
            int col = col0 + wc4 * 4;
            float4 wv = make_float4(0.f, 0.f, 0.f, 0.f);
            if (col < N)
                wv = *reinterpret_cast<const float4*>(&W[(size_t)(kt + wrow) * N + col]);
            *reinterpret_cast<float4*>(&Ws[wrow][wc4*4]) = wv;
        }
        __syncthreads();
        #pragma unroll
        for (int k = 0; k < BK; k++) {
            float a[8];
            float4 a0 = *reinterpret_cast<const float4*>(&As[k][ty*8]);
            float4 a1 = *reinterpret_cast<const float4*>(&As[k][ty*8+4]);
            a[0]=a0.x; a[1]=a0.y; a[2]=a0.z; a[3]=a0.w;
            a[4]=a1.x; a[5]=a1.y; a[6]=a1.z; a[7]=a1.w;
            float4 bv = *reinterpret_cast<const float4*>(&Ws[k][tx*4]);
            float b[4] = {bv.x, bv.y, bv.z, bv.w};
            #pragma unroll
            for (int i = 0; i < 8; i++)
                #pragma unroll
                for (int j = 0; j < 4; j++)
                    acc[i][j] = fmaf(a[i], b[j], acc[i][j]);
        }
        __syncthreads();
    }

    #pragma unroll
    for (int j = 0; j < 4; j++) {
        int col = col0 + tx * 4 + j;
        if (col >= N) continue;
        float bv = bias[col];
        #pragma unroll
        for (int i = 0; i < 8; i++) {
            int row = row0 + ty * 8 + i;
            float v = acc[i][j] + bv;
            if (EPI == 1) v = 0.5f * v * (1.f + erff(v * 0.70710678118654752f));
            C[(size_t)row * N + col] = v;
        }
    }
}

// ---------------- conv (causal depthwise K=4) + silu + dt/dA precompute -----
__global__ void conv_kernel(const float* __restrict__ z,
                            const float* __restrict__ convw,   // [576,4]
                            const float* __restrict__ convb,   // [576]
                            const float* __restrict__ dtb,     // [16]
                            const float* __restrict__ Alog,    // [16]
                            float* __restrict__ xbc,
                            float* __restrict__ dtO,
                            float* __restrict__ dAO)
{
    int tok = blockIdx.x;
    int b = tok >> 11, l = tok & 2047;
    for (int c = threadIdx.x; c < CONV_DIM + NHEADS; c += blockDim.x) {
        if (c < CONV_DIM) {
            float acc = convb[c];
            #pragma unroll
            for (int i = 0; i < KCONV; i++) {
                int ll = l - (KCONV - 1) + i;
                if (ll >= 0)
                    acc = fmaf(convw[c*KCONV + i],
                               z[(size_t)(b*SEQ + ll) * D_IN_PROJ + D_INNER + c], acc);
            }
            xbc[(size_t)tok * CONV_DIM + c] = siluf(acc);
        } else {
            int hh = c - CONV_DIM;
            float v = z[(size_t)tok * D_IN_PROJ + 2*D_INNER + 2*D_STATE + hh] + dtb[hh];
            float sp = (v > 20.f) ? v : log1pf(expf(v));
            dtO[tok*NHEADS + hh] = sp;
            dAO[tok*NHEADS + hh] = expf(-expf(Alog[hh]) * sp);
        }
    }
}

// ---------------- selective scan -------------------------------------------
// grid (16 heads, 16 batch), 128 threads: lane = p, warp w owns n in [8w,8w+8)
#define TT 32
__global__ void __launch_bounds__(128)
scan_kernel(const float* __restrict__ xbc, const float* __restrict__ dt,
            const float* __restrict__ dA, const float* __restrict__ Dv,
            float* __restrict__ y)
{
    int hI = blockIdx.x;
    int b  = blockIdx.y;
    int lane = threadIdx.x & 31;
    int w    = threadIdx.x >> 5;
    float Dh = Dv[hI];

    float hs[8];
    #pragma unroll
    for (int i = 0; i < 8; i++) hs[i] = 0.f;

    __shared__ float sB[TT][32];
    __shared__ float sC[TT][32];
    __shared__ float sdtx[TT][32];
    __shared__ float sxh[TT][32];
    __shared__ float sdA[TT];
    __shared__ float ypart[4][TT][32];

    for (int tile = 0; tile < SEQ / TT; tile++) {
        int t0 = b * SEQ + tile * TT;
        for (int j = threadIdx.x; j < TT * 32; j += 128) {
            int tl = j >> 5, c = j & 31;
            int tok = t0 + tl;
            const float* row = xbc + (size_t)tok * CONV_DIM;
            sB[tl][c] = row[D_INNER + c];
            sC[tl][c] = row[D_INNER + D_STATE + c];
            float xv = row[hI * HEADDIM + c];
            sxh[tl][c]  = xv;
            sdtx[tl][c] = dt[tok * NHEADS + hI] * xv;
        }
        if (threadIdx.x < TT)
            sdA[threadIdx.x] = dA[(t0 + threadIdx.x) * NHEADS + hI];
        __syncthreads();

        for (int tl = 0; tl < TT; tl++) {
            float a  = sdA[tl];
            float dx = sdtx[tl][lane];
            float acc = 0.f;
            #pragma unroll
            for (int i = 0; i < 8; i++) {
                int n = w * 8 + i;
                hs[i] = fmaf(hs[i], a, dx * sB[tl][n]);
                acc   = fmaf(hs[i], sC[tl][n], acc);
            }
            ypart[w][tl][lane] = acc;
        }
        __syncthreads();

        for (int j = threadIdx.x; j < TT * 32; j += 128) {
            int tl = j >> 5, p = j & 31;
            int tok = t0 + tl;
            float yv = ypart[0][tl][p] + ypart[1][tl][p] +
                       ypart[2][tl][p] + ypart[3][tl][p] + Dh * sxh[tl][p];
            y[(size_t)tok * D_INNER + hI * HEADDIM + p] = yv;
        }
        __syncthreads();
    }
}

// ---------------- gated RMSNorm: y = rmsnorm(y*silu(z), nw)  (512 wide) -----
__global__ void __launch_bounds__(256)
gatednorm_kernel(float* __restrict__ y, const float* __restrict__ zx,
                 const float* __restrict__ nw)
{
    int tok = blockIdx.x;
    float v[2]; float ss = 0.f;
    #pragma unroll
    for (int r = 0; r < 2; r++) {
        int c = threadIdx.x + r * 256;
        float zv = zx[(size_t)tok * D_IN_PROJ + c];
        float yv = y[(size_t)tok * D_INNER + c];
        v[r] = yv * siluf(zv);
        ss += v[r] * v[r];
    }
    ss = blockSum(ss);
    float scale = rsqrtf(ss / (float)D_INNER + EPS);
    #pragma unroll
    for (int r = 0; r < 2; r++) {
        int c = threadIdx.x + r * 256;
        y[(size_t)tok * D_INNER + c] = v[r] * scale * nw[c];
    }
}

// ---------------- residual + RMSNorm (256 wide): act = rmsnorm(o+act, w) ----
__global__ void __launch_bounds__(256)
resnorm_kernel(const float* __restrict__ o, float* __restrict__ act,
               const float* __restrict__ wgt)
{
    int tok = blockIdx.x, c = threadIdx.x;
    float v = o[(size_t)tok * HIDDEN + c] + act[(size_t)tok * HIDDEN + c];
    float ss = blockSum(v * v);
    act[(size_t)tok * HIDDEN + c] = v * rsqrtf(ss / (float)HIDDEN + EPS) * wgt[c];
}

// ---------------- LayerNorm (256 wide) --------------------------------------
__global__ void __launch_bounds__(256)
layernorm_kernel(const float* __restrict__ in, const float* __restrict__ w,
                 const float* __restrict__ bsl, float* __restrict__ out)
{
    int tok = blockIdx.x, c = threadIdx.x;
    float v = in[(size_t)tok * HIDDEN + c];
    float s  = blockSum(v);
    float s2 = blockSum(v * v);
    float m = s / (float)HIDDEN;
    float var = s2 / (float)HIDDEN - m * m;
    out[(size_t)tok * HIDDEN + c] = (v - m) * rsqrtf(var + EPS) * w[c] + bsl[c];
}

// ---------------- launch ----------------------------------------------------
extern "C" void kernel_launch(void* const* d_in, const int* in_sizes, int n_in,
                              void* d_out, int out_size)
{
    const float* x      = (const float*)d_in[0];
    const float* ip_w   = (const float*)d_in[1];
    const float* ip_b   = (const float*)d_in[2];
    const float* m_inw  = (const float*)d_in[3];
    const float* m_inb  = (const float*)d_in[4];
    const float* m_convw= (const float*)d_in[5];
    const float* m_convb= (const float*)d_in[6];
    const float* m_dtb  = (const float*)d_in[7];
    const float* m_Alog = (const float*)d_in[8];
    const float* m_D    = (const float*)d_in[9];
    const float* m_nw   = (const float*)d_in[10];
    const float* m_outw = (const float*)d_in[11];
    const float* m_outb = (const float*)d_in[12];
    const float* rms_w  = (const float*)d_in[13];
    const float* ln1_w  = (const float*)d_in[14];
    const float* ln1_b  = (const float*)d_in[15];
    const float* w1     = (const float*)d_in[16];
    const float* b1     = (const float*)d_in[17];
    const float* w2     = (const float*)d_in[18];
    const float* b2     = (const float*)d_in[19];
    const float* ln2_w  = (const float*)d_in[20];
    const float* ln2_b  = (const float*)d_in[21];
    float* out = (float*)d_out;

    float *act, *z, *xbc, *dt, *dA, *y, *o;
    cudaGetSymbolAddress((void**)&act, g_act);
    cudaGetSymbolAddress((void**)&z,   g_z);
    cudaGetSymbolAddress((void**)&xbc, g_xbc);
    cudaGetSymbolAddress((void**)&dt,  g_dt);
    cudaGetSymbolAddress((void**)&dA,  g_dA);
    cudaGetSymbolAddress((void**)&y,   g_y);
    cudaGetSymbolAddress((void**)&o,   g_o);

    const int MB = NTOK / 128;  // 256 row-blocks

    // input projection: act = x @ ip_w + ip_b
    sgemm_kernel<0><<<dim3(HIDDEN/64, MB), 256>>>(x, ip_w, ip_b, act,
                                                  NTOK, HIDDEN, INPUT_DIM);

    for (int i = 0; i < 2; i++) {
        // in-proj: z = act @ inw + inb   (N=1104)
        sgemm_kernel<0><<<dim3((D_IN_PROJ + 63) / 64, MB), 256>>>(
            act, m_inw + (size_t)i * HIDDEN * D_IN_PROJ, m_inb + i * D_IN_PROJ,
            z, NTOK, D_IN_PROJ, HIDDEN);
        // conv + silu + dt/dA
        conv_kernel<<<NTOK, 256>>>(z, m_convw + (size_t)i * CONV_DIM * KCONV,
                                   m_convb + i * CONV_DIM, m_dtb + i * NHEADS,
                                   m_Alog + i * NHEADS, xbc, dt, dA);
        // selective scan (+ D*xh)
        scan_kernel<<<dim3(NHEADS, BATCH), 128>>>(xbc, dt, dA, m_D + i * NHEADS, y);
        // gated rmsnorm (in place on y)
        gatednorm_kernel<<<NTOK, 256>>>(y, z, m_nw + i * D_INNER);
        // out-proj: o = y @ outw + outb
        sgemm_kernel<0><<<dim3(HIDDEN/64, MB), 256>>>(
            y, m_outw + (size_t)i * D_INNER * HIDDEN, m_outb + i * HIDDEN,
            o, NTOK, HIDDEN, D_INNER);
        // act = rmsnorm(o + act, rms_w)
        resnorm_kernel<<<NTOK, 256>>>(o, act, rms_w + i * HIDDEN);
    }

    // MLP head
    layernorm_kernel<<<NTOK, 256>>>(act, ln1_w, ln1_b, o);
    sgemm_kernel<1><<<dim3((2*HIDDEN)/64, MB), 256>>>(o, w1, b1, y,
                                                      NTOK, 2*HIDDEN, HIDDEN);   // gelu
    sgemm_kernel<0><<<dim3(HIDDEN/64, MB), 256>>>(y, w2, b2, o,
                                                  NTOK, HIDDEN, 2*HIDDEN);
    layernorm_kernel<<<NTOK, 256>>>(o, ln2_w, ln2_b, out);
}

// round 2
// speedup vs baseline: 1.7328x; 1.7328x over previous
#include <cuda_runtime.h>
#include <cuda_bf16.h>
#include <math.h>

// ---------------- problem constants ----------------
#define BATCH      16
#define SEQ        2048
#define NTOK       (BATCH*SEQ)          // 32768
#define INPUT_DIM  1024
#define HIDDEN     256
#define D_STATE    32
#define D_INNER    512
#define NHEADS     16
#define HEADDIM    32
#define CONV_DIM   576
#define D_IN_PROJ  1104
#define KCONV      4
#define EPS        1e-5f

// ---------------- scratch (device globals) ----------
__device__ __align__(128) float g_act [NTOK*HIDDEN];
__device__ __align__(128) float g_z   [NTOK*D_IN_PROJ];
__device__ __align__(128) float g_xbc [NTOK*CONV_DIM];
__device__ __align__(128) float g_dt  [NTOK*NHEADS];
__device__ __align__(128) float g_dA  [NTOK*NHEADS];
__device__ __align__(128) float g_y   [NTOK*D_INNER];
__device__ __align__(128) float g_o   [NTOK*HIDDEN];

// ---------------- helpers ----------------
__device__ __forceinline__ float blockSum(float v) {
    __shared__ float sh[8];
    __shared__ float total;
    int lane = threadIdx.x & 31, wid = threadIdx.x >> 5;
    #pragma unroll
    for (int o = 16; o > 0; o >>= 1) v += __shfl_xor_sync(0xffffffffu, v, o);
    if (lane == 0) sh[wid] = v;
    __syncthreads();
    if (threadIdx.x == 0) {
        float t = 0.f;
        int nw = (int)(blockDim.x >> 5);
        for (int i = 0; i < nw; i++) t += sh[i];
        total = t;
    }
    __syncthreads();
    return total;
}

__device__ __forceinline__ float siluf(float x) { return x / (1.f + expf(-x)); }

__device__ __forceinline__ unsigned f2tf(float x) {
    unsigned r;
    asm("cvt.rna.tf32.f32 %0, %1;" : "=r"(r) : "f"(x));
    return r;
}

// ---------------- TF32 tensor-core GEMM ------------------------------------
// C[M,N] = A[M,K] @ W[K,N] + bias ; EPI==1 -> exact GELU.
// BM=128 BN=64 BK=32, 256 threads = 8 warps (4x2), warp tile 32x32,
// mma.m16n8k8 tf32. A smem row-major [128][36] (conflict-free frag reads),
// B smem k-major [32][72].
template<int EPI>
__global__ void __launch_bounds__(256)
tgemm_kernel(const float* __restrict__ A, const float* __restrict__ W,
             const float* __restrict__ bias, float* __restrict__ C,
             int M, int N, int K)
{
    const int ASTR = 36, BSTR = 72;
    __shared__ unsigned As[128 * ASTR];   // 18.4 KB
    __shared__ unsigned Bs[32  * BSTR];   // 9.2 KB

    int tid = threadIdx.x, lane = tid & 31, warp = tid >> 5;
    int wm = warp >> 1, wn = warp & 1;
    int gid = lane >> 2, tig = lane & 3;
    int row0 = blockIdx.y * 128, col0 = blockIdx.x * 64;

    int akq = tid & 7,  arb = tid >> 3;   // A loader: 8 float4/row, 32 rows/pass
    int bnq = tid & 15, bkr = tid >> 4;   // B loader: 16 float4/row, 16 rows/pass

    const float* Abase = A + (size_t)row0 * K;

    float4 ra[4]; float4 rb[2];

    float acc[2][4][4];
    #pragma unroll
    for (int i = 0; i < 2; i++)
        #pragma unroll
        for (int j = 0; j < 4; j++)
            #pragma unroll
            for (int q = 0; q < 4; q++) acc[i][j][q] = 0.f;

    int bcol = col0 + bnq * 4;
    bool bok = (bcol < N);

    // prologue load
    {
        int kt = 0;
        #pragma unroll
        for (int p = 0; p < 4; p++)
            ra[p] = *reinterpret_cast<const float4*>(
                &Abase[(size_t)(arb + p*32) * K + kt + akq*4]);
        #pragma unroll
        for (int p = 0; p < 2; p++) {
            float4 v = make_float4(0.f,0.f,0.f,0.f);
            if (bok) v = *reinterpret_cast<const float4*>(
                &W[(size_t)(kt + bkr + p*16) * N + bcol]);
            rb[p] = v;
        }
    }
    // store stage 0
    #pragma unroll
    for (int p = 0; p < 4; p++) {
        uint4 u; u.x=f2tf(ra[p].x); u.y=f2tf(ra[p].y); u.z=f2tf(ra[p].z); u.w=f2tf(ra[p].w);
        *reinterpret_cast<uint4*>(&As[(arb + p*32)*ASTR + akq*4]) = u;
    }
    #pragma unroll
    for (int p = 0; p < 2; p++) {
        uint4 u; u.x=f2tf(rb[p].x); u.y=f2tf(rb[p].y); u.z=f2tf(rb[p].z); u.w=f2tf(rb[p].w);
        *reinterpret_cast<uint4*>(&Bs[(bkr + p*16)*BSTR + bnq*4]) = u;
    }
    __syncthreads();

    int nkt = K >> 5;
    for (int t = 0; t < nkt; t++) {
        // prefetch next tile into regs
        if (t + 1 < nkt) {
            int kt = (t + 1) << 5;
            #pragma unroll
            for (int p = 0; p < 4; p++)
                ra[p] = *reinterpret_cast<const float4*>(
                    &Abase[(size_t)(arb + p*32) * K + kt + akq*4]);
            #pragma unroll
            for (int p = 0; p < 2; p++) {
                float4 v = make_float4(0.f,0.f,0.f,0.f);
                if (bok) v = *reinterpret_cast<const float4*>(
                    &W[(size_t)(kt + bkr + p*16) * N + bcol]);
                rb[p] = v;
            }
        }

        // compute on current smem tile
        #pragma unroll
        for (int kc = 0; kc < 4; kc++) {
            unsigned af[2][4], bf[4][2];
            #pragma unroll
            for (int im = 0; im < 2; im++) {
                int base = (wm*32 + im*16 + gid)*ASTR + kc*8 + tig;
                af[im][0] = As[base];
                af[im][1] = As[base + 8*ASTR];
                af[im][2] = As[base + 4];
                af[im][3] = As[base + 8*ASTR + 4];
            }
            #pragma unroll
            for (int jn = 0; jn < 4; jn++) {
                int cb = wn*32 + jn*8 + gid;
                bf[jn][0] = Bs[(kc*8 + tig    )*BSTR + cb];
                bf[jn][1] = Bs[(kc*8 + tig + 4)*BSTR + cb];
            }
            #pragma unroll
            for (int im = 0; im < 2; im++)
                #pragma unroll
                for (int jn = 0; jn < 4; jn++) {
                    asm volatile(
                        "mma.sync.aligned.m16n8k8.row.col.f32.tf32.tf32.f32 "
                        "{%0,%1,%2,%3}, {%4,%5,%6,%7}, {%8,%9}, {%0,%1,%2,%3};"
                        : "+f"(acc[im][jn][0]), "+f"(acc[im][jn][1]),
                          "+f"(acc[im][jn][2]), "+f"(acc[im][jn][3])
                        : "r"(af[im][0]), "r"(af[im][1]),
                          "r"(af[im][2]), "r"(af[im][3]),
                          "r"(bf[jn][0]), "r"(bf[jn][1]));
                }
        }
        __syncthreads();

        if (t + 1 < nkt) {
            #pragma unroll
            for (int p = 0; p < 4; p++) {
                uint4 u; u.x=f2tf(ra[p].x); u.y=f2tf(ra[p].y); u.z=f2tf(ra[p].z); u.w=f2tf(ra[p].w);
                *reinterpret_cast<uint4*>(&As[(arb + p*32)*ASTR + akq*4]) = u;
            }
            #pragma unroll
            for (int p = 0; p < 2; p++) {
                uint4 u; u.x=f2tf(rb[p].x); u.y=f2tf(rb[p].y); u.z=f2tf(rb[p].z); u.w=f2tf(rb[p].w);
                *reinterpret_cast<uint4*>(&Bs[(bkr + p*16)*BSTR + bnq*4]) = u;
            }
            __syncthreads();
        }
    }

    // epilogue
    #pragma unroll
    for (int im = 0; im < 2; im++) {
        #pragma unroll
        for (int jn = 0; jn < 4; jn++) {
            int col = col0 + wn*32 + jn*8 + tig*2;
            if (col >= N) continue;
            float b0 = bias[col], b1 = bias[col + 1];
            int r0 = row0 + wm*32 + im*16 + gid;
            float v0 = acc[im][jn][0] + b0;
            float v1 = acc[im][jn][1] + b1;
            float v2 = acc[im][jn][2] + b0;
            float v3 = acc[im][jn][3] + b1;
            if (EPI == 1) {
                v0 = 0.5f*v0*(1.f + erff(v0*0.70710678118654752f));
                v1 = 0.5f*v1*(1.f + erff(v1*0.70710678118654752f));
                v2 = 0.5f*v2*(1.f + erff(v2*0.70710678118654752f));
                v3 = 0.5f*v3*(1.f + erff(v3*0.70710678118654752f));
            }
            *reinterpret_cast<float2*>(&C[(size_t)r0 * N + col]) = make_float2(v0, v1);
            *reinterpret_cast<float2*>(&C[(size_t)(r0+8) * N + col]) = make_float2(v2, v3);
        }
    }
}

// ---------------- conv (causal depthwise K=4) + silu + dt/dA ---------------
__global__ void conv_kernel(const float* __restrict__ z,
                            const float* __restrict__ convw,
                            const float* __restrict__ convb,
                            const float* __restrict__ dtb,
                            const float* __restrict__ Alog,
                            float* __restrict__ xbc,
                            float* __restrict__ dtO,
                            float* __restrict__ dAO)
{
    int tok = blockIdx.x;
    int b = tok >> 11, l = tok & 2047;
    for (int c = threadIdx.x; c < CONV_DIM + NHEADS; c += blockDim.x) {
        if (c < CONV_DIM) {
            float acc = convb[c];
            #pragma unroll
            for (int i = 0; i < KCONV; i++) {
                int ll = l - (KCONV - 1) + i;
                if (ll >= 0)
                    acc = fmaf(convw[c*KCONV + i],
                               z[(size_t)(b*SEQ + ll) * D_IN_PROJ + D_INNER + c], acc);
            }
            xbc[(size_t)tok * CONV_DIM + c] = siluf(acc);
        } else {
            int hh = c - CONV_DIM;
            float v = z[(size_t)tok * D_IN_PROJ + 2*D_INNER + 2*D_STATE + hh] + dtb[hh];
            float sp = (v > 20.f) ? v : log1pf(expf(v));
            dtO[tok*NHEADS + hh] = sp;
            dAO[tok*NHEADS + hh] = expf(-expf(Alog[hh]) * sp);
        }
    }
}

// ---------------- selective scan -------------------------------------------
// grid (16 heads, 16 batch), 256 threads: lane = p, warp w owns n in [4w,4w+4)
#define TT 32
__global__ void __launch_bounds__(256)
scan_kernel(const float* __restrict__ xbc, const float* __restrict__ dt,
            const float* __restrict__ dA, const float* __restrict__ Dv,
            float* __restrict__ y)
{
    int hI = blockIdx.x;
    int b  = blockIdx.y;
    int lane = threadIdx.x & 31;
    int w    = threadIdx.x >> 5;      // 0..7
    float Dh = Dv[hI];

    float hs[4];
    #pragma unroll
    for (int i = 0; i < 4; i++) hs[i] = 0.f;

    __shared__ float sB[TT][32];
    __shared__ float sC[TT][32];
    __shared__ float sdtx[TT][32];
    __shared__ float sxh[TT][32];
    __shared__ float sdA[TT];
    __shared__ float ypart[8][TT][32];

    for (int tile = 0; tile < SEQ / TT; tile++) {
        int t0 = b * SEQ + tile * TT;
        for (int j = threadIdx.x; j < TT * 32; j += 256) {
            int tl = j >> 5, c = j & 31;
            int tok = t0 + tl;
            const float* row = xbc + (size_t)tok * CONV_DIM;
            sB[tl][c] = row[D_INNER + c];
            sC[tl][c] = row[D_INNER + D_STATE + c];
            float xv = row[hI * HEADDIM + c];
            sxh[tl][c]  = xv;
            sdtx[tl][c] = dt[tok * NHEADS + hI] * xv;
        }
        if (threadIdx.x < TT)
            sdA[threadIdx.x] = dA[(t0 + threadIdx.x) * NHEADS + hI];
        __syncthreads();

        for (int tl = 0; tl < TT; tl++) {
            float a  = sdA[tl];
            float dx = sdtx[tl][lane];
            float acc = 0.f;
            #pragma unroll
            for (int i = 0; i < 4; i++) {
                int n = w * 4 + i;
                hs[i] = fmaf(hs[i], a, dx * sB[tl][n]);
                acc   = fmaf(hs[i], sC[tl][n], acc);
            }
            ypart[w][tl][lane] = acc;
        }
        __syncthreads();

        for (int j = threadIdx.x; j < TT * 32; j += 256) {
            int tl = j >> 5, p = j & 31;
            int tok = t0 + tl;
            float yv = ypart[0][tl][p] + ypart[1][tl][p] +
                       ypart[2][tl][p] + ypart[3][tl][p] +
                       ypart[4][tl][p] + ypart[5][tl][p] +
                       ypart[6][tl][p] + ypart[7][tl][p] + Dh * sxh[tl][p];
            y[(size_t)tok * D_INNER + hI * HEADDIM + p] = yv;
        }
        __syncthreads();
    }
}

// ---------------- gated RMSNorm --------------------------------------------
__global__ void __launch_bounds__(256)
gatednorm_kernel(float* __restrict__ y, const float* __restrict__ zx,
                 const float* __restrict__ nw)
{
    int tok = blockIdx.x;
    float v[2]; float ss = 0.f;
    #pragma unroll
    for (int r = 0; r < 2; r++) {
        int c = threadIdx.x + r * 256;
        float zv = zx[(size_t)tok * D_IN_PROJ + c];
        float yv = y[(size_t)tok * D_INNER + c];
        v[r] = yv * siluf(zv);
        ss += v[r] * v[r];
    }
    ss = blockSum(ss);
    float scale = rsqrtf(ss / (float)D_INNER + EPS);
    #pragma unroll
    for (int r = 0; r < 2; r++) {
        int c = threadIdx.x + r * 256;
        y[(size_t)tok * D_INNER + c] = v[r] * scale * nw[c];
    }
}

// ---------------- residual + RMSNorm ---------------------------------------
__global__ void __launch_bounds__(256)
resnorm_kernel(const float* __restrict__ o, float* __restrict__ act,
               const float* __restrict__ wgt)
{
    int tok = blockIdx.x, c = threadIdx.x;
    float v = o[(size_t)tok * HIDDEN + c] + act[(size_t)tok * HIDDEN + c];
    float ss = blockSum(v * v);
    act[(size_t)tok * HIDDEN + c] = v * rsqrtf(ss / (float)HIDDEN + EPS) * wgt[c];
}

// ---------------- LayerNorm ------------------------------------------------
__global__ void __launch_bounds__(256)
layernorm_kernel(const float* __restrict__ in, const float* __restrict__ w,
                 const float* __restrict__ bsl, float* __restrict__ out)
{
    int tok = blockIdx.x, c = threadIdx.x;
    float v = in[(size_t)tok * HIDDEN + c];
    float s  = blockSum(v);
    float s2 = blockSum(v * v);
    float m = s / (float)HIDDEN;
    float var = s2 / (float)HIDDEN - m * m;
    out[(size_t)tok * HIDDEN + c] = (v - m) * rsqrtf(var + EPS) * w[c] + bsl[c];
}

// ---------------- launch ----------------------------------------------------
extern "C" void kernel_launch(void* const* d_in, const int* in_sizes, int n_in,
                              void* d_out, int out_size)
{
    const float* x      = (const float*)d_in[0];
    const float* ip_w   = (const float*)d_in[1];
    const float* ip_b   = (const float*)d_in[2];
    const float* m_inw  = (const float*)d_in[3];
    const float* m_inb  = (const float*)d_in[4];
    const float* m_convw= (const float*)d_in[5];
    const float* m_convb= (const float*)d_in[6];
    const float* m_dtb  = (const float*)d_in[7];
    const float* m_Alog = (const float*)d_in[8];
    const float* m_D    = (const float*)d_in[9];
    const float* m_nw   = (const float*)d_in[10];
    const float* m_outw = (const float*)d_in[11];
    const float* m_outb = (const float*)d_in[12];
    const float* rms_w  = (const float*)d_in[13];
    const float* ln1_w  = (const float*)d_in[14];
    const float* ln1_b  = (const float*)d_in[15];
    const float* w1     = (const float*)d_in[16];
    const float* b1     = (const float*)d_in[17];
    const float* w2     = (const float*)d_in[18];
    const float* b2     = (const float*)d_in[19];
    const float* ln2_w  = (const float*)d_in[20];
    const float* ln2_b  = (const float*)d_in[21];
    float* out = (float*)d_out;

    float *act, *z, *xbc, *dt, *dA, *y, *o;
    cudaGetSymbolAddress((void**)&act, g_act);
    cudaGetSymbolAddress((void**)&z,   g_z);
    cudaGetSymbolAddress((void**)&xbc, g_xbc);
    cudaGetSymbolAddress((void**)&dt,  g_dt);
    cudaGetSymbolAddress((void**)&dA,  g_dA);
    cudaGetSymbolAddress((void**)&y,   g_y);
    cudaGetSymbolAddress((void**)&o,   g_o);

    const int MB = NTOK / 128;  // 256 row-blocks

    // input projection: act = x @ ip_w + ip_b
    tgemm_kernel<0><<<dim3(HIDDEN/64, MB), 256>>>(x, ip_w, ip_b, act,
                                                  NTOK, HIDDEN, INPUT_DIM);

    for (int i = 0; i < 2; i++) {
        tgemm_kernel<0><<<dim3((D_IN_PROJ + 63) / 64, MB), 256>>>(
            act, m_inw + (size_t)i * HIDDEN * D_IN_PROJ, m_inb + i * D_IN_PROJ,
            z, NTOK, D_IN_PROJ, HIDDEN);
        conv_kernel<<<NTOK, 256>>>(z, m_convw + (size_t)i * CONV_DIM * KCONV,
                                   m_convb + i * CONV_DIM, m_dtb + i * NHEADS,
                                   m_Alog + i * NHEADS, xbc, dt, dA);
        scan_kernel<<<dim3(NHEADS, BATCH), 256>>>(xbc, dt, dA, m_D + i * NHEADS, y);
        gatednorm_kernel<<<NTOK, 256>>>(y, z, m_nw + i * D_INNER);
        tgemm_kernel<0><<<dim3(HIDDEN/64, MB), 256>>>(
            y, m_outw + (size_t)i * D_INNER * HIDDEN, m_outb + i * HIDDEN,
            o, NTOK, HIDDEN, D_INNER);
        resnorm_kernel<<<NTOK, 256>>>(o, act, rms_w + i * HIDDEN);
    }

    // MLP head
    layernorm_kernel<<<NTOK, 256>>>(act, ln1_w, ln1_b, o);
    tgemm_kernel<1><<<dim3((2*HIDDEN)/64, MB), 256>>>(o, w1, b1, y,
                                                      NTOK, 2*HIDDEN, HIDDEN);
    tgemm_kernel<0><<<dim3(HIDDEN/64, MB), 256>>>(y, w2, b2, o,
                                                  NTOK, HIDDEN, 2*HIDDEN);
    layernorm_kernel<<<NTOK, 256>>>(o, ln2_w, ln2_b, out);
}

// round 4
// speedup vs baseline: 1.7654x; 1.0188x over previous
#include <cuda_runtime.h>
#include <cuda_bf16.h>
#include <math.h>

// ---------------- problem constants ----------------
#define BATCH      16
#define SEQ        2048
#define NTOK       (BATCH*SEQ)          // 32768
#define INPUT_DIM  1024
#define HIDDEN     256
#define D_STATE    32
#define D_INNER    512
#define NHEADS     16
#define HEADDIM    32
#define CONV_DIM   576
#define D_IN_PROJ  1104
#define KCONV      4
#define EPS        1e-5f
#define CHUNK      128
#define NCH        (SEQ/CHUNK)          // 16

// ---------------- scratch (device globals) ----------
__device__ __align__(128) float g_act [NTOK*HIDDEN];
__device__ __align__(128) float g_z   [NTOK*D_IN_PROJ];
__device__ __align__(128) float g_xbc [NTOK*CONV_DIM];
__device__ __align__(128) float g_dt  [NTOK*NHEADS];
__device__ __align__(128) float g_dA  [NTOK*NHEADS];
__device__ __align__(128) float g_y   [NTOK*D_INNER];
__device__ __align__(128) float g_o   [NTOK*HIDDEN];
__device__ __align__(128) float g_cum [NTOK*NHEADS];                     // per-token decay prefix
__device__ __align__(128) float g_F   [BATCH*NHEADS*NCH*32*32];          // chunk-final local states
__device__ __align__(128) float g_Hin [BATCH*NHEADS*NCH*32*32];          // chunk initial states

// ---------------- helpers ----------------
__device__ __forceinline__ float blockSum(float v) {
    __shared__ float sh[8];
    __shared__ float total;
    int lane = threadIdx.x & 31, wid = threadIdx.x >> 5;
    #pragma unroll
    for (int o = 16; o > 0; o >>= 1) v += __shfl_xor_sync(0xffffffffu, v, o);
    if (lane == 0) sh[wid] = v;
    __syncthreads();
    if (threadIdx.x == 0) {
        float t = 0.f;
        int nw = (int)(blockDim.x >> 5);
        for (int i = 0; i < nw; i++) t += sh[i];
        total = t;
    }
    __syncthreads();
    return total;
}

__device__ __forceinline__ float siluf(float x) { return x / (1.f + expf(-x)); }

__device__ __forceinline__ unsigned f2tf(float x) {
    unsigned r;
    asm("cvt.rna.tf32.f32 %0, %1;" : "=r"(r) : "f"(x));
    return r;
}

// ---------------- TF32 tensor-core GEMM (FROZEN from round 2) --------------
template<int EPI>
__global__ void __launch_bounds__(256)
tgemm_kernel(const float* __restrict__ A, const float* __restrict__ W,
             const float* __restrict__ bias, float* __restrict__ C,
             int M, int N, int K)
{
    const int ASTR = 36, BSTR = 72;
    __shared__ unsigned As[128 * ASTR];
    __shared__ unsigned Bs[32  * BSTR];

    int tid = threadIdx.x, lane = tid & 31, warp = tid >> 5;
    int wm = warp >> 1, wn = warp & 1;
    int gid = lane >> 2, tig = lane & 3;
    int row0 = blockIdx.y * 128, col0 = blockIdx.x * 64;

    int akq = tid & 7,  arb = tid >> 3;
    int bnq = tid & 15, bkr = tid >> 4;

    const float* Abase = A + (size_t)row0 * K;

    float4 ra[4]; float4 rb[2];

    float acc[2][4][4];
    #pragma unroll
    for (int i = 0; i < 2; i++)
        #pragma unroll
        for (int j = 0; j < 4; j++)
            #pragma unroll
            for (int q = 0; q < 4; q++) acc[i][j][q] = 0.f;

    int bcol = col0 + bnq * 4;
    bool bok = (bcol < N);

    {
        int kt = 0;
        #pragma unroll
        for (int p = 0; p < 4; p++)
            ra[p] = *reinterpret_cast<const float4*>(
                &Abase[(size_t)(arb + p*32) * K + kt + akq*4]);
        #pragma unroll
        for (int p = 0; p < 2; p++) {
            float4 v = make_float4(0.f,0.f,0.f,0.f);
            if (bok) v = *reinterpret_cast<const float4*>(
                &W[(size_t)(kt + bkr + p*16) * N + bcol]);
            rb[p] = v;
        }
    }
    #pragma unroll
    for (int p = 0; p < 4; p++) {
        uint4 u; u.x=f2tf(ra[p].x); u.y=f2tf(ra[p].y); u.z=f2tf(ra[p].z); u.w=f2tf(ra[p].w);
        *reinterpret_cast<uint4*>(&As[(arb + p*32)*ASTR + akq*4]) = u;
    }
    #pragma unroll
    for (int p = 0; p < 2; p++) {
        uint4 u; u.x=f2tf(rb[p].x); u.y=f2tf(rb[p].y); u.z=f2tf(rb[p].z); u.w=f2tf(rb[p].w);
        *reinterpret_cast<uint4*>(&Bs[(bkr + p*16)*BSTR + bnq*4]) = u;
    }
    __syncthreads();

    int nkt = K >> 5;
    for (int t = 0; t < nkt; t++) {
        if (t + 1 < nkt) {
            int kt = (t + 1) << 5;
            #pragma unroll
            for (int p = 0; p < 4; p++)
                ra[p] = *reinterpret_cast<const float4*>(
                    &Abase[(size_t)(arb + p*32) * K + kt + akq*4]);
            #pragma unroll
            for (int p = 0; p < 2; p++) {
                float4 v = make_float4(0.f,0.f,0.f,0.f);
                if (bok) v = *reinterpret_cast<const float4*>(
                    &W[(size_t)(kt + bkr + p*16) * N + bcol]);
                rb[p] = v;
            }
        }

        #pragma unroll
        for (int kc = 0; kc < 4; kc++) {
            unsigned af[2][4], bf[4][2];
            #pragma unroll
            for (int im = 0; im < 2; im++) {
                int base = (wm*32 + im*16 + gid)*ASTR + kc*8 + tig;
                af[im][0] = As[base];
                af[im][1] = As[base + 8*ASTR];
                af[im][2] = As[base + 4];
                af[im][3] = As[base + 8*ASTR + 4];
            }
            #pragma unroll
            for (int jn = 0; jn < 4; jn++) {
                int cb = wn*32 + jn*8 + gid;
                bf[jn][0] = Bs[(kc*8 + tig    )*BSTR + cb];
                bf[jn][1] = Bs[(kc*8 + tig + 4)*BSTR + cb];
            }
            #pragma unroll
            for (int im = 0; im < 2; im++)
                #pragma unroll
                for (int jn = 0; jn < 4; jn++) {
                    asm volatile(
                        "mma.sync.aligned.m16n8k8.row.col.f32.tf32.tf32.f32 "
                        "{%0,%1,%2,%3}, {%4,%5,%6,%7}, {%8,%9}, {%0,%1,%2,%3};"
                        : "+f"(acc[im][jn][0]), "+f"(acc[im][jn][1]),
                          "+f"(acc[im][jn][2]), "+f"(acc[im][jn][3])
                        : "r"(af[im][0]), "r"(af[im][1]),
                          "r"(af[im][2]), "r"(af[im][3]),
                          "r"(bf[jn][0]), "r"(bf[jn][1]));
                }
        }
        __syncthreads();

        if (t + 1 < nkt) {
            #pragma unroll
            for (int p = 0; p < 4; p++) {
                uint4 u; u.x=f2tf(ra[p].x); u.y=f2tf(ra[p].y); u.z=f2tf(ra[p].z); u.w=f2tf(ra[p].w);
                *reinterpret_cast<uint4*>(&As[(arb + p*32)*ASTR + akq*4]) = u;
            }
            #pragma unroll
            for (int p = 0; p < 2; p++) {
                uint4 u; u.x=f2tf(rb[p].x); u.y=f2tf(rb[p].y); u.z=f2tf(rb[p].z); u.w=f2tf(rb[p].w);
                *reinterpret_cast<uint4*>(&Bs[(bkr + p*16)*BSTR + bnq*4]) = u;
            }
            __syncthreads();
        }
    }

    #pragma unroll
    for (int im = 0; im < 2; im++) {
        #pragma unroll
        for (int jn = 0; jn < 4; jn++) {
            int col = col0 + wn*32 + jn*8 + tig*2;
            if (col >= N) continue;
            float b0 = bias[col], b1 = bias[col + 1];
            int r0 = row0 + wm*32 + im*16 + gid;
            float v0 = acc[im][jn][0] + b0;
            float v1 = acc[im][jn][1] + b1;
            float v2 = acc[im][jn][2] + b0;
            float v3 = acc[im][jn][3] + b1;
            if (EPI == 1) {
                v0 = 0.5f*v0*(1.f + erff(v0*0.70710678118654752f));
                v1 = 0.5f*v1*(1.f + erff(v1*0.70710678118654752f));
                v2 = 0.5f*v2*(1.f + erff(v2*0.70710678118654752f));
                v3 = 0.5f*v3*(1.f + erff(v3*0.70710678118654752f));
            }
            *reinterpret_cast<float2*>(&C[(size_t)r0 * N + col]) = make_float2(v0, v1);
            *reinterpret_cast<float2*>(&C[(size_t)(r0+8) * N + col]) = make_float2(v2, v3);
        }
    }
}

// ---------------- conv (causal depthwise K=4) + silu + dt/dA ---------------
__global__ void conv_kernel(const float* __restrict__ z,
                            const float* __restrict__ convw,
                            const float* __restrict__ convb,
                            const float* __restrict__ dtb,
                            const float* __restrict__ Alog,
                            float* __restrict__ xbc,
                            float* __restrict__ dtO,
                            float* __restrict__ dAO)
{
    int tok = blockIdx.x;
    int b = tok >> 11, l = tok & 2047;
    for (int c = threadIdx.x; c < CONV_DIM + NHEADS; c += blockDim.x) {
        if (c < CONV_DIM) {
            float acc = convb[c];
            #pragma unroll
            for (int i = 0; i < KCONV; i++) {
                int ll = l - (KCONV - 1) + i;
                if (ll >= 0)
                    acc = fmaf(convw[c*KCONV + i],
                               z[(size_t)(b*SEQ + ll) * D_IN_PROJ + D_INNER + c], acc);
            }
            xbc[(size_t)tok * CONV_DIM + c] = siluf(acc);
        } else {
            int hh = c - CONV_DIM;
            float v = z[(size_t)tok * D_IN_PROJ + 2*D_INNER + 2*D_STATE + hh] + dtb[hh];
            float sp = (v > 20.f) ? v : log1pf(expf(v));
            dtO[tok*NHEADS + hh] = sp;
            dAO[tok*NHEADS + hh] = expf(-expf(Alog[hh]) * sp);
        }
    }
}

// ---------------- chunked selective scan: pass 1 (local scans) -------------
// grid (16 heads, 16 batch, 16 chunks), 128 threads: lane=p, warp w owns n in [8w,8w+8)
#define TT 32
__global__ void __launch_bounds__(128)
scan_local_kernel(const float* __restrict__ xbc, const float* __restrict__ dt,
                  const float* __restrict__ dA, const float* __restrict__ Dv,
                  float* __restrict__ y, float* __restrict__ cumO,
                  float* __restrict__ F)
{
    int hI = blockIdx.x;
    int b  = blockIdx.y;
    int ch = blockIdx.z;
    int lane = threadIdx.x & 31;
    int w    = threadIdx.x >> 5;
    float Dh = Dv[hI];

    float hs[8];
    #pragma unroll
    for (int i = 0; i < 8; i++) hs[i] = 0.f;
    float cum = 1.f;

    __shared__ float sB[TT][32];
    __shared__ float sC[TT][32];
    __shared__ float sdtx[TT][32];
    __shared__ float sxh[TT][32];
    __shared__ float sdA[TT];
    __shared__ float scum[TT];
    __shared__ float ypart[4][TT][32];

    int tchunk0 = b * SEQ + ch * CHUNK;

    for (int tile = 0; tile < CHUNK / TT; tile++) {
        int t0 = tchunk0 + tile * TT;
        for (int j = threadIdx.x; j < TT * 32; j += 128) {
            int tl = j >> 5, c = j & 31;
            int tok = t0 + tl;
            const float* row = xbc + (size_t)tok * CONV_DIM;
            sB[tl][c] = row[D_INNER + c];
            sC[tl][c] = row[D_INNER + D_STATE + c];
            float xv = row[hI * HEADDIM + c];
            sxh[tl][c]  = xv;
            sdtx[tl][c] = dt[tok * NHEADS + hI] * xv;
        }
        if (threadIdx.x < TT)
            sdA[threadIdx.x] = dA[(t0 + threadIdx.x) * NHEADS + hI];
        __syncthreads();

        for (int tl = 0; tl < TT; tl++) {
            float a  = sdA[tl];
            cum *= a;
            float dx = sdtx[tl][lane];
            float acc = 0.f;
            #pragma unroll
            for (int i = 0; i < 8; i++) {
                int n = w * 8 + i;
                hs[i] = fmaf(hs[i], a, dx * sB[tl][n]);
                acc   = fmaf(hs[i], sC[tl][n], acc);
            }
            ypart[w][tl][lane] = acc;
            if (threadIdx.x == 0) scum[tl] = cum;
        }
        __syncthreads();

        for (int j = threadIdx.x; j < TT * 32; j += 128) {
            int tl = j >> 5, p = j & 31;
            int tok = t0 + tl;
            float yv = ypart[0][tl][p] + ypart[1][tl][p] +
                       ypart[2][tl][p] + ypart[3][tl][p] + Dh * sxh[tl][p];
            y[(size_t)tok * D_INNER + hI * HEADDIM + p] = yv;
            if (p == 0) cumO[tok * NHEADS + hI] = scum[tl];
        }
        __syncthreads();
    }

    // write final local state F[b][h][ch][n][p]
    size_t fbase = (size_t)(((b * NHEADS + hI) * NCH + ch)) * 1024;
    #pragma unroll
    for (int i = 0; i < 8; i++) {
        int n = w * 8 + i;
        F[fbase + n * 32 + lane] = hs[i];
    }
}

// ---------------- pass 2: combine chunk states -----------------------------
// grid (16 heads, 16 batch), 256 threads, each owns one float4 of the 32x32 state
__global__ void __launch_bounds__(256)
scan_combine_kernel(const float* __restrict__ F, const float* __restrict__ cum,
                    float* __restrict__ Hin)
{
    int hI = blockIdx.x, b = blockIdx.y;
    size_t base = (size_t)((b * NHEADS + hI) * NCH) * 1024;
    int off = threadIdx.x * 4;
    float4 hr = make_float4(0.f, 0.f, 0.f, 0.f);
    for (int c = 0; c < NCH; c++) {
        *reinterpret_cast<float4*>(&Hin[base + (size_t)c * 1024 + off]) = hr;
        float P = cum[(size_t)(b * SEQ + c * CHUNK + CHUNK - 1) * NHEADS + hI];
        float4 f = *reinterpret_cast<const float4*>(&F[base + (size_t)c * 1024 + off]);
        hr.x = fmaf(hr.x, P, f.x);
        hr.y = fmaf(hr.y, P, f.y);
        hr.z = fmaf(hr.z, P, f.z);
        hr.w = fmaf(hr.w, P, f.w);
    }
}

// ---------------- pass 3: apply chunk-initial-state correction -------------
// grid (16 heads, 16 batch, 16 chunks), 128 threads (4 warps x 32 tokens each)
__global__ void __launch_bounds__(128)
scan_fix_kernel(const float* __restrict__ xbc, const float* __restrict__ cum,
                const float* __restrict__ Hin, float* __restrict__ y)
{
    int hI = blockIdx.x, b = blockIdx.y, ch = blockIdx.z;
    if (ch == 0) return;
    int lane = threadIdx.x & 31, w = threadIdx.x >> 5;

    __shared__ float sh[32][32];
    size_t base = (size_t)(((b * NHEADS + hI) * NCH + ch)) * 1024;
    for (int j = threadIdx.x; j < 1024; j += 128)
        sh[j >> 5][j & 31] = Hin[base + j];
    __syncthreads();

    int t0 = b * SEQ + ch * CHUNK + w * 32;
    for (int tt = 0; tt < 32; tt++) {
        int tok = t0 + tt;
        float cv = xbc[(size_t)tok * CONV_DIM + D_INNER + D_STATE + lane];
        float pt = cum[tok * NHEADS + hI];
        float a0 = 0.f, a1 = 0.f;
        #pragma unroll
        for (int n = 0; n < 32; n += 2) {
            a0 = fmaf(__shfl_sync(0xffffffffu, cv, n),     sh[n][lane],     a0);
            a1 = fmaf(__shfl_sync(0xffffffffu, cv, n + 1), sh[n + 1][lane], a1);
        }
        y[(size_t)tok * D_INNER + hI * HEADDIM + lane] += pt * (a0 + a1);
    }
}

// ---------------- gated RMSNorm --------------------------------------------
__global__ void __launch_bounds__(256)
gatednorm_kernel(float* __restrict__ y, const float* __restrict__ zx,
                 const float* __restrict__ nw)
{
    int tok = blockIdx.x;
    float v[2]; float ss = 0.f;
    #pragma unroll
    for (int r = 0; r < 2; r++) {
        int c = threadIdx.x + r * 256;
        float zv = zx[(size_t)tok * D_IN_PROJ + c];
        float yv = y[(size_t)tok * D_INNER + c];
        v[r] = yv * siluf(zv);
        ss += v[r] * v[r];
    }
    ss = blockSum(ss);
    float scale = rsqrtf(ss / (float)D_INNER + EPS);
    #pragma unroll
    for (int r = 0; r < 2; r++) {
        int c = threadIdx.x + r * 256;
        y[(size_t)tok * D_INNER + c] = v[r] * scale * nw[c];
    }
}

// ---------------- residual + RMSNorm ---------------------------------------
__global__ void __launch_bounds__(256)
resnorm_kernel(const float* __restrict__ o, float* __restrict__ act,
               const float* __restrict__ wgt)
{
    int tok = blockIdx.x, c = threadIdx.x;
    float v = o[(size_t)tok * HIDDEN + c] + act[(size_t)tok * HIDDEN + c];
    float ss = blockSum(v * v);
    act[(size_t)tok * HIDDEN + c] = v * rsqrtf(ss / (float)HIDDEN + EPS) * wgt[c];
}

// ---------------- LayerNorm ------------------------------------------------
__global__ void __launch_bounds__(256)
layernorm_kernel(const float* __restrict__ in, const float* __restrict__ w,
                 const float* __restrict__ bsl, float* __restrict__ out)
{
    int tok = blockIdx.x, c = threadIdx.x;
    float v = in[(size_t)tok * HIDDEN + c];
    float s  = blockSum(v);
    float s2 = blockSum(v * v);
    float m = s / (float)HIDDEN;
    float var = s2 / (float)HIDDEN - m * m;
    out[(size_t)tok * HIDDEN + c] = (v - m) * rsqrtf(var + EPS) * w[c] + bsl[c];
}

// ---------------- launch ----------------------------------------------------
extern "C" void kernel_launch(void* const* d_in, const int* in_sizes, int n_in,
                              void* d_out, int out_size)
{
    const float* x      = (const float*)d_in[0];
    const float* ip_w   = (const float*)d_in[1];
    const float* ip_b   = (const float*)d_in[2];
    const float* m_inw  = (const float*)d_in[3];
    const float* m_inb  = (const float*)d_in[4];
    const float* m_convw= (const float*)d_in[5];
    const float* m_convb= (const float*)d_in[6];
    const float* m_dtb  = (const float*)d_in[7];
    const float* m_Alog = (const float*)d_in[8];
    const float* m_D    = (const float*)d_in[9];
    const float* m_nw   = (const float*)d_in[10];
    const float* m_outw = (const float*)d_in[11];
    const float* m_outb = (const float*)d_in[12];
    const float* rms_w  = (const float*)d_in[13];
    const float* ln1_w  = (const float*)d_in[14];
    const float* ln1_b  = (const float*)d_in[15];
    const float* w1     = (const float*)d_in[16];
    const float* b1     = (const float*)d_in[17];
    const float* w2     = (const float*)d_in[18];
    const float* b2     = (const float*)d_in[19];
    const float* ln2_w  = (const float*)d_in[20];
    const float* ln2_b  = (const float*)d_in[21];
    float* out = (float*)d_out;

    float *act, *z, *xbc, *dt, *dA, *y, *o, *cum, *F, *Hin;
    cudaGetSymbolAddress((void**)&act, g_act);
    cudaGetSymbolAddress((void**)&z,   g_z);
    cudaGetSymbolAddress((void**)&xbc, g_xbc);
    cudaGetSymbolAddress((void**)&dt,  g_dt);
    cudaGetSymbolAddress((void**)&dA,  g_dA);
    cudaGetSymbolAddress((void**)&y,   g_y);
    cudaGetSymbolAddress((void**)&o,   g_o);
    cudaGetSymbolAddress((void**)&cum, g_cum);
    cudaGetSymbolAddress((void**)&F,   g_F);
    cudaGetSymbolAddress((void**)&Hin, g_Hin);

    const int MB = NTOK / 128;

    tgemm_kernel<0><<<dim3(HIDDEN/64, MB), 256>>>(x, ip_w, ip_b, act,
                                                  NTOK, HIDDEN, INPUT_DIM);

    for (int i = 0; i < 2; i++) {
        tgemm_kernel<0><<<dim3((D_IN_PROJ + 63) / 64, MB), 256>>>(
            act, m_inw + (size_t)i * HIDDEN * D_IN_PROJ, m_inb + i * D_IN_PROJ,
            z, NTOK, D_IN_PROJ, HIDDEN);
        conv_kernel<<<NTOK, 256>>>(z, m_convw + (size_t)i * CONV_DIM * KCONV,
                                   m_convb + i * CONV_DIM, m_dtb + i * NHEADS,
                                   m_Alog + i * NHEADS, xbc, dt, dA);
        scan_local_kernel<<<dim3(NHEADS, BATCH, NCH), 128>>>(
            xbc, dt, dA, m_D + i * NHEADS, y, cum, F);
        scan_combine_kernel<<<dim3(NHEADS, BATCH), 256>>>(F, cum, Hin);
        scan_fix_kernel<<<dim3(NHEADS, BATCH, NCH), 128>>>(xbc, cum, Hin, y);
        gatednorm_kernel<<<NTOK, 256>>>(y, z, m_nw + i * D_INNER);
        tgemm_kernel<0><<<dim3(HIDDEN/64, MB), 256>>>(
            y, m_outw + (size_t)i * D_INNER * HIDDEN, m_outb + i * HIDDEN,
            o, NTOK, HIDDEN, D_INNER);
        resnorm_kernel<<<NTOK, 256>>>(o, act, rms_w + i * HIDDEN);
    }

    layernorm_kernel<<<NTOK, 256>>>(act, ln1_w, ln1_b, o);
    tgemm_kernel<1><<<dim3((2*HIDDEN)/64, MB), 256>>>(o, w1, b1, y,
                                                      NTOK, 2*HIDDEN, HIDDEN);
    tgemm_kernel<0><<<dim3(HIDDEN/64, MB), 256>>>(y, w2, b2, o,
                                                  NTOK, HIDDEN, 2*HIDDEN);
    layernorm_kernel<<<NTOK, 256>>>(o, ln2_w, ln2_b, out);
}